// round 1
// baseline (speedup 1.0000x reference)
#include <cuda_runtime.h>
#include <math.h>

#define Nn 50000
#define Ee 800000
#define INF 128
#define HIDf 96
#define Hh 8
#define Dd 12
#define Gg 64
#define OUTf 10
#define NB_SCAN ((Nn + 511) / 512)   // 98

// ---------------- scratch (device globals; no allocation allowed) ------------
__device__ __align__(16) float g_tmp[Nn * HIDf];
__device__ __align__(16) float g_h0[Nn * HIDf];
__device__ __align__(16) float g_h1[Nn * HIDf];
__device__ __align__(16) float g_fs[Nn * HIDf];
__device__ __align__(16) float g_fd[Nn * HIDf];
__device__ __align__(16) float g_logits[Ee * Hh];
__device__ int   g_degout[Nn];
__device__ int   g_degin[Nn];
__device__ int   g_fill[Nn];
__device__ int   g_rowptr[Nn + 1];
__device__ int   g_esrc[Ee];
__device__ int   g_edst[Ee];
__device__ int   g_part[128];
__device__ int   g_hg[Gg * HIDf];
__device__ float g_dinvout[Nn];
__device__ float g_dinvin[Nn];

// ---------------- init ----------------
__global__ void k_init() {
    int i = blockIdx.x * blockDim.x + threadIdx.x;
    if (i < Nn) { g_degout[i] = 0; g_degin[i] = 0; g_fill[i] = 0; }
    if (i < Gg * HIDf) g_hg[i] = 0;   // bits of +0.0f; all readout inputs are >= 0
}

// ---------------- degrees / histogram ----------------
__global__ void k_degree(const int* __restrict__ src, const int* __restrict__ dst) {
    int e = blockIdx.x * blockDim.x + threadIdx.x;
    if (e < Ee) {
        atomicAdd(&g_degout[src[e]], 1);
        atomicAdd(&g_degin[dst[e]], 1);
    }
}

// ---------------- exclusive scan of g_degin -> g_rowptr ----------------
__global__ void k_scan1() {
    __shared__ int s[512];
    int t = threadIdx.x;
    int idx = blockIdx.x * 512 + t;
    int v = (idx < Nn) ? g_degin[idx] : 0;
    s[t] = v;
    __syncthreads();
    for (int off = 1; off < 512; off <<= 1) {
        int x = (t >= off) ? s[t - off] : 0;
        __syncthreads();
        s[t] += x;
        __syncthreads();
    }
    if (idx < Nn) g_rowptr[idx] = s[t] - v;     // exclusive within block
    if (t == 511) g_part[blockIdx.x] = s[511];  // block sum
}

__global__ void k_scan2() {
    __shared__ int s[128];
    int t = threadIdx.x;  // 128
    int v = (t < NB_SCAN) ? g_part[t] : 0;
    s[t] = v;
    __syncthreads();
    for (int off = 1; off < 128; off <<= 1) {
        int x = (t >= off) ? s[t - off] : 0;
        __syncthreads();
        s[t] += x;
        __syncthreads();
    }
    if (t < NB_SCAN) g_part[t] = s[t] - v;      // exclusive block offsets
}

__global__ void k_scan3() {
    int idx = blockIdx.x * blockDim.x + threadIdx.x;
    if (idx < Nn) g_rowptr[idx] += g_part[idx >> 9];
    if (idx == 0) g_rowptr[Nn] = Ee;
}

// ---------------- deg^-0.5 (clamped >= 1) ----------------
__global__ void k_dinv() {
    int i = blockIdx.x * blockDim.x + threadIdx.x;
    if (i < Nn) {
        g_dinvout[i] = rsqrtf((float)max(g_degout[i], 1));
        g_dinvin[i]  = rsqrtf((float)max(g_degin[i], 1));
    }
}

// ---------------- CSR fill (edges sorted by dst) ----------------
__global__ void k_fill(const int* __restrict__ src, const int* __restrict__ dst) {
    int e = blockIdx.x * blockDim.x + threadIdx.x;
    if (e < Ee) {
        int d = dst[e];
        int pos = g_rowptr[d] + atomicAdd(&g_fill[d], 1);
        g_esrc[pos] = src[e];
        g_edst[pos] = d;
    }
}

// ---------------- GEMM: out[N,96] = (in [* dinvout]) @ W [+ bias] ----------------
// block tile 64 rows x 96 cols, threads (24,16), 4x4 micro-tile
__global__ void k_gemm(const float* __restrict__ in, const float* __restrict__ W,
                       const float* __restrict__ bias, int use_rowscale,
                       float* __restrict__ out, int kin) {
    __shared__ float sW[32][HIDf];
    __shared__ float sIn[64][33];
    int tx = threadIdx.x;            // 0..23 -> cols 4*tx..4*tx+3
    int ty = threadIdx.y;            // 0..15 -> rows 4*ty..4*ty+3
    int tid = ty * 24 + tx;          // 0..383
    int rowBase = blockIdx.x * 64;
    float acc[4][4] = {};

    for (int kc = 0; kc < kin; kc += 32) {
        for (int i = tid; i < 32 * HIDf; i += 384) {
            int kk = i / HIDf, cc = i % HIDf;
            sW[kk][cc] = W[(kc + kk) * HIDf + cc];
        }
        for (int i = tid; i < 64 * 32; i += 384) {
            int r = i >> 5, k = i & 31;
            int row = rowBase + r;
            float v = 0.f;
            if (row < Nn) {
                v = in[row * kin + kc + k];
                if (use_rowscale) v *= g_dinvout[row];
            }
            sIn[r][k] = v;
        }
        __syncthreads();
#pragma unroll
        for (int k = 0; k < 32; k++) {
            float4 b = *(const float4*)&sW[k][tx * 4];
#pragma unroll
            for (int i = 0; i < 4; i++) {
                float a = sIn[ty * 4 + i][k];
                acc[i][0] += a * b.x;
                acc[i][1] += a * b.y;
                acc[i][2] += a * b.z;
                acc[i][3] += a * b.w;
            }
        }
        __syncthreads();
    }
#pragma unroll
    for (int i = 0; i < 4; i++) {
        int row = rowBase + ty * 4 + i;
        if (row < Nn) {
            float4 o;
            float b0 = 0.f, b1 = 0.f, b2 = 0.f, b3 = 0.f;
            if (bias) {
                b0 = bias[tx * 4 + 0]; b1 = bias[tx * 4 + 1];
                b2 = bias[tx * 4 + 2]; b3 = bias[tx * 4 + 3];
            }
            o.x = acc[i][0] + b0; o.y = acc[i][1] + b1;
            o.z = acc[i][2] + b2; o.w = acc[i][3] + b3;
            *(float4*)(out + row * HIDf + tx * 4) = o;
        }
    }
}

// ---------------- GraphConv aggregation: out = relu(sum_in(pre[src]) * dinvin + b)
// one warp per node; lane l owns features l, l+32, l+64
__global__ void k_agg(const float* __restrict__ pre, const float* __restrict__ bias,
                      float* __restrict__ out) {
    int warp = (blockIdx.x * blockDim.x + threadIdx.x) >> 5;
    int lane = threadIdx.x & 31;
    if (warp >= Nn) return;
    int beg = g_rowptr[warp], end = g_rowptr[warp + 1];
    float a0 = 0.f, a1 = 0.f, a2 = 0.f;
    for (int p = beg; p < end; p++) {
        const float* r = pre + g_esrc[p] * HIDf;
        a0 += r[lane];
        a1 += r[lane + 32];
        a2 += r[lane + 64];
    }
    float sc = g_dinvin[warp];
    out[warp * HIDf + lane]      = fmaxf(a0 * sc + bias[lane], 0.f);
    out[warp * HIDf + lane + 32] = fmaxf(a1 * sc + bias[lane + 32], 0.f);
    out[warp * HIDf + lane + 64] = fmaxf(a2 * sc + bias[lane + 64], 0.f);
}

// ---------------- GATv2 edge logits (dst-sorted order) ----------------
// thread = (sorted edge p, head h); logit = sum_d lrelu(fs[s]+fd[d]) * attn[h,d]
__global__ void k_logits(const float* __restrict__ attn) {
    int idx = blockIdx.x * blockDim.x + threadIdx.x;
    if (idx >= Ee * Hh) return;
    int p = idx >> 3, h = idx & 7;
    int s = g_esrc[p], d = g_edst[p];
    const float4* fsp = (const float4*)(g_fs + s * HIDf + h * Dd);
    const float4* fdp = (const float4*)(g_fd + d * HIDf + h * Dd);
    float lg = 0.f;
#pragma unroll
    for (int j = 0; j < 3; j++) {
        float4 a = fsp[j];
        float4 b = fdp[j];
        float v;
        v = a.x + b.x; v = (v > 0.f) ? v : 0.2f * v; lg += v * __ldg(attn + h * Dd + j * 4 + 0);
        v = a.y + b.y; v = (v > 0.f) ? v : 0.2f * v; lg += v * __ldg(attn + h * Dd + j * 4 + 1);
        v = a.z + b.z; v = (v > 0.f) ? v : 0.2f * v; lg += v * __ldg(attn + h * Dd + j * 4 + 2);
        v = a.w + b.w; v = (v > 0.f) ? v : 0.2f * v; lg += v * __ldg(attn + h * Dd + j * 4 + 3);
    }
    g_logits[idx] = lg;   // idx == p*8 + h
}

// ---------------- GATv2 per-node softmax + weighted sum + relu ----------------
// one warp per node. Phase 1/2: per-head max/den (lane = 4 edge-subgroups x 8 heads).
// Phase 3: lane l accumulates features l, l+32, l+64.
__global__ void k_gatnode(float* __restrict__ out) {
    int warp = (blockIdx.x * blockDim.x + threadIdx.x) >> 5;
    int lane = threadIdx.x & 31;
    if (warp >= Nn) return;
    int beg = g_rowptr[warp], end = g_rowptr[warp + 1];
    int h = lane & 7, sub = lane >> 3;

    float mh = -3.402823466e38f;
    for (int p = beg + sub; p < end; p += 4) mh = fmaxf(mh, g_logits[p * 8 + h]);
    mh = fmaxf(mh, __shfl_xor_sync(0xffffffffu, mh, 8));
    mh = fmaxf(mh, __shfl_xor_sync(0xffffffffu, mh, 16));

    float den = 0.f;
    for (int p = beg + sub; p < end; p += 4) den += __expf(g_logits[p * 8 + h] - mh);
    den += __shfl_xor_sync(0xffffffffu, den, 8);
    den += __shfl_xor_sync(0xffffffffu, den, 16);
    // now every lane holds (mh, den) for head = lane & 7; lanes 0..7 hold heads 0..7

    int f0 = lane, f1 = lane + 32, f2 = lane + 64;
    int h0 = f0 / Dd, h1 = f1 / Dd, h2 = f2 / Dd;
    float m0 = __shfl_sync(0xffffffffu, mh, h0);
    float m1 = __shfl_sync(0xffffffffu, mh, h1);
    float m2 = __shfl_sync(0xffffffffu, mh, h2);
    float d0 = __shfl_sync(0xffffffffu, den, h0);
    float d1 = __shfl_sync(0xffffffffu, den, h1);
    float d2 = __shfl_sync(0xffffffffu, den, h2);
    float r0 = (d0 > 0.f) ? 1.f / d0 : 0.f;
    float r1 = (d1 > 0.f) ? 1.f / d1 : 0.f;
    float r2 = (d2 > 0.f) ? 1.f / d2 : 0.f;

    float acc0 = 0.f, acc1 = 0.f, acc2 = 0.f;
    for (int p = beg; p < end; p++) {
        const float* lg = g_logits + p * 8;
        float a0 = __expf(lg[h0] - m0) * r0;
        float a1 = __expf(lg[h1] - m1) * r1;
        float a2 = __expf(lg[h2] - m2) * r2;
        const float* fr = g_fs + g_esrc[p] * HIDf;
        acc0 += a0 * fr[f0];
        acc1 += a1 * fr[f1];
        acc2 += a2 * fr[f2];
    }
    out[warp * HIDf + f0] = fmaxf(acc0, 0.f);
    out[warp * HIDf + f1] = fmaxf(acc1, 0.f);
    out[warp * HIDf + f2] = fmaxf(acc2, 0.f);
}

// ---------------- per-graph max readout (values >= 0 after relu) ----------------
__global__ void k_readout(const float* __restrict__ hfin, const int* __restrict__ gid) {
    __shared__ int s[Gg * HIDf];
    int tid = threadIdx.x;  // 384
    for (int i = tid; i < Gg * HIDf; i += 384) s[i] = 0;
    __syncthreads();
    int f = tid % 96, rr = tid / 96;  // rr in 0..3
    for (int node = blockIdx.x * 4 + rr; node < Nn; node += 64 * 4) {
        int g = gid[node];
        float v = hfin[node * HIDf + f];
        atomicMax(&s[g * HIDf + f], __float_as_int(v));  // v >= 0 -> int order = float order
    }
    __syncthreads();
    for (int i = tid; i < Gg * HIDf; i += 384) atomicMax(&g_hg[i], s[i]);
}

// ---------------- classifier MLP on [64,96] ----------------
__global__ void k_mlp(const float* __restrict__ Wc1, const float* __restrict__ bc1,
                      const float* __restrict__ Wc2, const float* __restrict__ bc2,
                      const float* __restrict__ Wc3, const float* __restrict__ bc3,
                      float* __restrict__ out) {
    __shared__ float A[Gg * HIDf];
    __shared__ float B[Gg * HIDf];
    int tid = threadIdx.x;  // 512
    for (int i = tid; i < Gg * HIDf; i += 512) A[i] = __int_as_float(g_hg[i]);
    __syncthreads();
    // z1 = relu(A @ Wc1 + bc1) -> B   [64,96]
    for (int i = tid; i < Gg * HIDf; i += 512) {
        int r = i / 96, c = i % 96;
        float acc = bc1[c];
        for (int k = 0; k < 96; k++) acc += A[r * 96 + k] * Wc1[k * 96 + c];
        B[i] = fmaxf(acc, 0.f);
    }
    __syncthreads();
    // z2 = relu(B @ Wc2 + bc2) -> A   [64,48]
    for (int i = tid; i < Gg * 48; i += 512) {
        int r = i / 48, c = i % 48;
        float acc = bc2[c];
        for (int k = 0; k < 96; k++) acc += B[r * 96 + k] * Wc2[k * 48 + c];
        A[i] = fmaxf(acc, 0.f);
    }
    __syncthreads();
    // out = A @ Wc3 + bc3   [64,10]
    for (int i = tid; i < Gg * OUTf; i += 512) {
        int r = i / 10, c = i % 10;
        float acc = bc3[c];
        for (int k = 0; k < 48; k++) acc += A[r * 48 + k] * Wc3[k * 10 + c];
        out[i] = acc;
    }
}

// ---------------- host launcher ----------------
extern "C" void kernel_launch(void* const* d_in, const int* in_sizes, int n_in,
                              void* d_out, int out_size) {
    (void)in_sizes; (void)n_in; (void)out_size;
    const float* x    = (const float*)d_in[0];
    const int*   src  = (const int*)d_in[1];
    const int*   dst  = (const int*)d_in[2];
    const int*   gid  = (const int*)d_in[3];
    const float* W1   = (const float*)d_in[4];
    const float* b1   = (const float*)d_in[5];
    const float* W2   = (const float*)d_in[6];
    const float* b2   = (const float*)d_in[7];
    const float* Ws   = (const float*)d_in[8];
    const float* bs   = (const float*)d_in[9];
    const float* Wd   = (const float*)d_in[10];
    const float* bd   = (const float*)d_in[11];
    const float* attn = (const float*)d_in[12];
    const float* Wc1  = (const float*)d_in[13];
    const float* bc1  = (const float*)d_in[14];
    const float* Wc2  = (const float*)d_in[15];
    const float* bc2  = (const float*)d_in[16];
    const float* Wc3  = (const float*)d_in[17];
    const float* bc3  = (const float*)d_in[18];
    float* out = (float*)d_out;

    float *p_tmp, *p_h0, *p_h1, *p_fs, *p_fd;
    cudaGetSymbolAddress((void**)&p_tmp, g_tmp);
    cudaGetSymbolAddress((void**)&p_h0, g_h0);
    cudaGetSymbolAddress((void**)&p_h1, g_h1);
    cudaGetSymbolAddress((void**)&p_fs, g_fs);
    cudaGetSymbolAddress((void**)&p_fd, g_fd);

    const int TPB = 256;
    dim3 gb(24, 16);
    int gemm_blocks = (Nn + 63) / 64;          // 782
    int warp_blocks = (Nn * 32 + TPB - 1) / TPB;  // 6250
    int edge_blocks = (Ee + TPB - 1) / TPB;    // 3125
    int logit_blocks = (Ee * Hh + TPB - 1) / TPB;  // 25000

    k_init<<<(Nn + TPB - 1) / TPB, TPB>>>();
    k_degree<<<edge_blocks, TPB>>>(src, dst);
    k_scan1<<<NB_SCAN, 512>>>();
    k_scan2<<<1, 128>>>();
    k_scan3<<<NB_SCAN, 512>>>();
    k_dinv<<<(Nn + TPB - 1) / TPB, TPB>>>();
    k_fill<<<edge_blocks, TPB>>>(src, dst);

    // GraphConv 1: x[N,128] -> h0
    k_gemm<<<gemm_blocks, gb>>>(x, W1, nullptr, 1, p_tmp, INF);
    k_agg<<<warp_blocks, TPB>>>(p_tmp, b1, p_h0);
    // GraphConv 2: h0 -> h1
    k_gemm<<<gemm_blocks, gb>>>(p_h0, W2, nullptr, 1, p_tmp, HIDf);
    k_agg<<<warp_blocks, TPB>>>(p_tmp, b2, p_h1);

    // 3x GATv2: h1 -> h0 -> h1 -> h0
    float* hin = p_h1;
    float* hout = p_h0;
    for (int i = 0; i < 3; i++) {
        k_gemm<<<gemm_blocks, gb>>>(hin, Ws + i * HIDf * HIDf, bs + i * HIDf, 0, p_fs, HIDf);
        k_gemm<<<gemm_blocks, gb>>>(hin, Wd + i * HIDf * HIDf, bd + i * HIDf, 0, p_fd, HIDf);
        k_logits<<<logit_blocks, TPB>>>(attn + i * Hh * Dd);
        k_gatnode<<<warp_blocks, TPB>>>(hout);
        float* t = hin; hin = hout; hout = t;
    }
    // final features are in `hin` (= h0 after 3 layers)

    k_readout<<<64, 384>>>(hin, gid);
    k_mlp<<<1, 512>>>(Wc1, bc1, Wc2, bc2, Wc3, bc3, out);
}